// round 2
// baseline (speedup 1.0000x reference)
#include <cuda_runtime.h>
#include <math.h>

// Problem constants
#define Bc 4
#define Tc 2048
#define Ec 64
#define Hc 8
#define QLc 6
#define BHc (Bc*Hc)
#define CAP 768          // max active columns per row (analysis bound: 384)

// Static device scratch (allocation-free rule)
__device__ float g_Q[BHc*Tc*Ec];     // 16 MB, layout [b,h,t,e]
__device__ float g_K[BHc*Tc*Ec];     // 16 MB
__device__ float g_V[BHc*Tc*Ec];     // 16 MB
__device__ float g_ATT[BHc*Tc*Ec];   // 16 MB
__device__ unsigned short g_cols[Tc*CAP];
__device__ int g_cnt[Tc];

// ---------------------------------------------------------------------------
// Build per-row active-column lists by replicating _row_mask(index, 64, 2048)
// exactly (log_l = ceil(log2(64)) = 6). Does NOT read the mask input, so the
// harness's bool-dtype representation is irrelevant.
// Dense rows (row < 384): cols 0..row.
// Sparse rows: per 64-stride iteration, range [idx-5, idx] plus points at
// idx-6-2^i (i=0..5); terminal edge emits [0, idx) EXCLUSIVE, per reference.
// Emitted descending (provably duplicate-free), then reversed.
// ---------------------------------------------------------------------------
__global__ void build_cols() {
    int row = blockIdx.x * blockDim.x + threadIdx.x;
    if (row >= Tc) return;
    const int log_l = 6, sub = 64;
    unsigned short* out = g_cols + row * CAP;

    if ((Tc / sub) * 2 * log_l > row) {           // 384 > row: dense causal
        for (int j = 0; j <= row; j++) out[j] = (unsigned short)j;
        g_cnt[row] = row + 1;
        return;
    }

    unsigned short tmp[CAP];
    int cnt = 0;
    int index = row;
    while (index >= 0) {
        if (index - log_l + 1 < 0) {
            for (int j = index - 1; j >= 0; j--) tmp[cnt++] = (unsigned short)j;
            break;
        }
        for (int j = index; j >= index - log_l + 1; j--)
            tmp[cnt++] = (unsigned short)j;
        for (int i = 0; i < log_l; i++) {
            int ni = index - log_l + 1 - (1 << i);
            if (index - ni <= sub && ni >= 0) tmp[cnt++] = (unsigned short)ni;
        }
        index -= sub;
    }
    for (int j = 0; j < cnt; j++) out[j] = tmp[cnt - 1 - j];
    g_cnt[row] = cnt;
}

// ---------------------------------------------------------------------------
// V projection: value = x @ Wv + bv, stored as [b,h,t,e]
// ---------------------------------------------------------------------------
__global__ void proj_v(const float* __restrict__ x,
                       const float* __restrict__ Wv,
                       const float* __restrict__ bv) {
    int bt = blockIdx.x;                // b*T + t
    __shared__ float xs[Ec];
    int tid = threadIdx.x;              // 128 threads
    if (tid < Ec) xs[tid] = x[(size_t)bt * Ec + tid];
    __syncthreads();
    float acc[4] = {0.f, 0.f, 0.f, 0.f};
    for (int i = 0; i < Ec; i++) {
        float xv = xs[i];
        const float* wr = Wv + (size_t)i * (Hc * Ec);
        #pragma unroll
        for (int a = 0; a < 4; a++) acc[a] += xv * wr[tid + a * 128];
    }
    int b = bt / Tc, t = bt % Tc;
    #pragma unroll
    for (int a = 0; a < 4; a++) {
        int o = tid + a * 128;
        int h = o >> 6, e = o & 63;
        g_V[(((size_t)b * Hc + h) * Tc + t) * Ec + e] = acc[a] + bv[o];
    }
}

// ---------------------------------------------------------------------------
// Causal conv1d QK projection (im2col-style tiled GEMM):
// qk[b,o,t] = bqk[o] + sum_{i<64,j<6} x[b, t-5+j, i] * Wqk[o,i,j]
// o-tile = 16 channels, t-tile = 64, 128 threads, 2o x 4t register blocking.
// ---------------------------------------------------------------------------
__global__ void proj_qk(const float* __restrict__ x,
                        const float* __restrict__ Wqk,
                        const float* __restrict__ bqk) {
    __shared__ float Ws[16][385];   // kk = j*64 + i ordering, padded
    __shared__ float Xs[69][65];    // rows t0-5 .. t0+63, padded
    int b  = blockIdx.z;
    int o0 = blockIdx.y * 16;
    int t0 = blockIdx.x * 64;
    int tid = threadIdx.x;

    for (int idx = tid; idx < 16 * 384; idx += 128) {
        int oo = idx / 384, kk = idx % 384;
        int j = kk >> 6, i = kk & 63;
        Ws[oo][kk] = Wqk[(size_t)(o0 + oo) * 384 + i * QLc + j];
    }
    for (int idx = tid; idx < 69 * 64; idx += 128) {
        int rr = idx >> 6, i = idx & 63;
        int t = t0 - 5 + rr;
        Xs[rr][i] = (t >= 0) ? x[((size_t)b * Tc + t) * Ec + i] : 0.f;
    }
    __syncthreads();

    int ox = tid & 7;    // 8 groups, 2 channels each
    int tx = tid >> 3;   // 16 groups, 4 timesteps each
    float acc[2][4];
    #pragma unroll
    for (int a = 0; a < 2; a++)
        #pragma unroll
        for (int bb = 0; bb < 4; bb++) acc[a][bb] = 0.f;

    for (int kk = 0; kk < 384; kk++) {
        int j = kk >> 6, i = kk & 63;
        float w0 = Ws[ox * 2 + 0][kk];
        float w1 = Ws[ox * 2 + 1][kk];
        #pragma unroll
        for (int bb = 0; bb < 4; bb++) {
            float xv = Xs[tx * 4 + bb + j][i];
            acc[0][bb] += w0 * xv;
            acc[1][bb] += w1 * xv;
        }
    }
    #pragma unroll
    for (int a = 0; a < 2; a++) {
        int ch = o0 + ox * 2 + a;
        float bias = bqk[ch];
        int hh = (ch & 511) >> 6, e = ch & 63;
        float* dst = (ch < 512 ? g_Q : g_K) +
                     ((size_t)b * Hc + hh) * Tc * Ec + e;
        #pragma unroll
        for (int bb = 0; bb < 4; bb++) {
            int t = t0 + tx * 4 + bb;
            dst[(size_t)t * Ec] = acc[a][bb] + bias;
        }
    }
}

// ---------------------------------------------------------------------------
// Sparse masked attention: one warp per query row.
// Computes scores only on active columns, exact softmax (masked = 0.0f,
// matching fp32 exp underflow of the -1e9 reference path), writes normalized
// weights scattered into the pre-zeroed output, accumulates PV.
// ---------------------------------------------------------------------------
__global__ void attn_kernel(float* __restrict__ wout_base) {
    __shared__ float qs[8][64];
    __shared__ float sc[8][CAP];
    int w = threadIdx.x >> 5;
    int lane = threadIdx.x & 31;
    int r = blockIdx.x * 8 + w;
    int bh = blockIdx.y;

    const float* Qrow = g_Q + ((size_t)bh * Tc + r) * Ec;
    qs[w][lane]      = Qrow[lane];
    qs[w][lane + 32] = Qrow[lane + 32];
    __syncwarp();

    int cnt = g_cnt[r];
    const unsigned short* cl = g_cols + r * CAP;
    const float* Kb = g_K + (size_t)bh * Tc * Ec;

    float m = -1e30f;
    for (int jj = lane; jj < cnt; jj += 32) {
        int c = cl[jj];
        const float4* kr = (const float4*)(Kb + (size_t)c * Ec);
        float s = 0.f;
        #pragma unroll
        for (int q4 = 0; q4 < 16; q4++) {
            float4 kv = kr[q4];
            s += qs[w][q4 * 4 + 0] * kv.x + qs[w][q4 * 4 + 1] * kv.y
               + qs[w][q4 * 4 + 2] * kv.z + qs[w][q4 * 4 + 3] * kv.w;
        }
        s *= 0.125f;                  // 1/sqrt(64)
        sc[w][jj] = s;
        m = fmaxf(m, s);
    }
    #pragma unroll
    for (int off = 16; off; off >>= 1)
        m = fmaxf(m, __shfl_xor_sync(0xffffffffu, m, off));

    float sum = 0.f;
    for (int jj = lane; jj < cnt; jj += 32) {
        float e = __expf(sc[w][jj] - m);
        sc[w][jj] = e;
        sum += e;
    }
    #pragma unroll
    for (int off = 16; off; off >>= 1)
        sum += __shfl_xor_sync(0xffffffffu, sum, off);
    float inv = __fdividef(1.f, sum);
    __syncwarp();

    // scattered weight writes (rest of the row is already zero)
    float* wout = wout_base + ((size_t)bh * Tc + r) * Tc;
    for (int jj = lane; jj < cnt; jj += 32)
        wout[cl[jj]] = sc[w][jj] * inv;

    // PV accumulate: lanes own e-dims, coalesced V row reads
    const float* Vb = g_V + (size_t)bh * Tc * Ec;
    float o0 = 0.f, o1 = 0.f;
    int jj = 0;
    for (; jj + 4 <= cnt; jj += 4) {
        #pragma unroll
        for (int u = 0; u < 4; u++) {
            float wg = sc[w][jj + u];
            const float* vr = Vb + (size_t)cl[jj + u] * Ec;
            o0 += wg * vr[lane];
            o1 += wg * vr[lane + 32];
        }
    }
    for (; jj < cnt; jj++) {
        float wg = sc[w][jj];
        const float* vr = Vb + (size_t)cl[jj] * Ec;
        o0 += wg * vr[lane];
        o1 += wg * vr[lane + 32];
    }
    float* ar = g_ATT + ((size_t)bh * Tc + r) * Ec;
    ar[lane]      = o0 * inv;
    ar[lane + 32] = o1 * inv;
}

// ---------------------------------------------------------------------------
// Output projection: out[b,t,:] = attn_flat[b,t,:] @ Wp + bp
// attn_flat[b,t,h*64+e] = g_ATT[b,h,t,e]. Block handles 4 (b,t) rows.
// ---------------------------------------------------------------------------
__global__ void proj_out(const float* __restrict__ Wp,
                         const float* __restrict__ bp,
                         float* __restrict__ out) {
    __shared__ float as[4][520];
    int base_bt = blockIdx.x * 4;
    int tid = threadIdx.x;   // 256
    for (int idx = tid; idx < 4 * 512; idx += 256) {
        int rr = idx >> 9, c = idx & 511;
        int bt = base_bt + rr;
        int b = bt / Tc, t = bt % Tc;
        int h = c >> 6, e = c & 63;
        as[rr][c] = g_ATT[(((size_t)b * Hc + h) * Tc + t) * Ec + e];
    }
    __syncthreads();
    int rr = tid >> 6, eo = tid & 63;
    float acc = bp[eo];
    for (int c = 0; c < 512; c++)
        acc += as[rr][c] * Wp[(size_t)c * Ec + eo];
    out[(size_t)(base_bt + rr) * Ec + eo] = acc;
}

// ---------------------------------------------------------------------------
extern "C" void kernel_launch(void* const* d_in, const int* in_sizes, int n_in,
                              void* d_out, int out_size) {
    const float* x    = (const float*)d_in[0];
    const float* Wqk  = (const float*)d_in[1];
    const float* bqk  = (const float*)d_in[2];
    const float* Wv   = (const float*)d_in[3];
    const float* bv   = (const float*)d_in[4];
    const float* Wp   = (const float*)d_in[5];
    const float* bp   = (const float*)d_in[6];
    // d_in[7] (mask) intentionally unused: regenerated on-device from the
    // deterministic _row_mask algorithm to avoid bool-dtype ambiguity.

    float* out = (float*)d_out;
    float* weights = out + (size_t)Bc * Tc * Ec;  // attn_weights after out

    // Zero whole output: masked attn weights are exactly 0.0f in the reference
    cudaMemsetAsync(d_out, 0, (size_t)out_size * sizeof(float), 0);

    build_cols<<<(Tc + 127) / 128, 128>>>();
    proj_v<<<Bc * Tc, 128>>>(x, Wv, bv);
    dim3 gqk(Tc / 64, 1024 / 16, Bc);
    proj_qk<<<gqk, 128>>>(x, Wqk, bqk);
    dim3 ga(Tc / 8, BHc);
    attn_kernel<<<ga, 256>>>(weights);
    proj_out<<<Bc * Tc / 4, 256>>>(Wp, bp, out);
}

// round 3
// speedup vs baseline: 1.6350x; 1.6350x over previous
#include <cuda_runtime.h>
#include <math.h>

// Problem constants
#define Bc 4
#define Tc 2048
#define Ec 64
#define Hc 8
#define QLc 6
#define BHc (Bc*Hc)
#define CAP 416          // max active columns per row (analysis bound: 384)

// Static device scratch (allocation-free rule)
__device__ float g_Q[BHc*Tc*Ec];     // 16 MB, layout [b,h,t,e]
__device__ float g_K[BHc*Tc*Ec];     // 16 MB
__device__ float g_V[BHc*Tc*Ec];     // 16 MB
__device__ float g_ATT[BHc*Tc*Ec];   // 16 MB
__device__ unsigned short g_cols[Tc*CAP];
__device__ int g_cnt[Tc];

// ---------------------------------------------------------------------------
// Build per-row active-column lists by replicating _row_mask(index, 64, 2048)
// exactly (log_l = 6). Mask input is never read (dtype-agnostic).
// ---------------------------------------------------------------------------
__global__ void build_cols() {
    int row = blockIdx.x * blockDim.x + threadIdx.x;
    if (row >= Tc) return;
    const int log_l = 6, sub = 64;
    unsigned short* out = g_cols + row * CAP;

    if ((Tc / sub) * 2 * log_l > row) {           // 384 > row: dense causal
        for (int j = 0; j <= row; j++) out[j] = (unsigned short)j;
        g_cnt[row] = row + 1;
        return;
    }

    unsigned short tmp[CAP];
    int cnt = 0;
    int index = row;
    while (index >= 0) {
        if (index - log_l + 1 < 0) {
            for (int j = index - 1; j >= 0; j--) tmp[cnt++] = (unsigned short)j;
            break;
        }
        for (int j = index; j >= index - log_l + 1; j--)
            tmp[cnt++] = (unsigned short)j;
        for (int i = 0; i < log_l; i++) {
            int ni = index - log_l + 1 - (1 << i);
            if (index - ni <= sub && ni >= 0) tmp[cnt++] = (unsigned short)ni;
        }
        index -= sub;
    }
    for (int j = 0; j < cnt; j++) out[j] = tmp[cnt - 1 - j];
    g_cnt[row] = cnt;
}

// ---------------------------------------------------------------------------
// V projection: value = x @ Wv + bv, stored as [b,h,t,e]
// ---------------------------------------------------------------------------
__global__ void proj_v(const float* __restrict__ x,
                       const float* __restrict__ Wv,
                       const float* __restrict__ bv) {
    int bt = blockIdx.x;                // b*T + t
    __shared__ float xs[Ec];
    int tid = threadIdx.x;              // 128 threads
    if (tid < Ec) xs[tid] = x[(size_t)bt * Ec + tid];
    __syncthreads();
    float acc[4] = {0.f, 0.f, 0.f, 0.f};
    for (int i = 0; i < Ec; i++) {
        float xv = xs[i];
        const float* wr = Wv + (size_t)i * (Hc * Ec);
        #pragma unroll
        for (int a = 0; a < 4; a++) acc[a] += xv * wr[tid + a * 128];
    }
    int b = bt / Tc, t = bt % Tc;
    #pragma unroll
    for (int a = 0; a < 4; a++) {
        int o = tid + a * 128;
        int h = o >> 6, e = o & 63;
        g_V[(((size_t)b * Hc + h) * Tc + t) * Ec + e] = acc[a] + bv[o];
    }
}

// ---------------------------------------------------------------------------
// Causal conv1d QK projection (im2col-style tiled GEMM)
// ---------------------------------------------------------------------------
__global__ void proj_qk(const float* __restrict__ x,
                        const float* __restrict__ Wqk,
                        const float* __restrict__ bqk) {
    __shared__ float Ws[16][385];   // kk = j*64 + i ordering, padded
    __shared__ float Xs[69][65];    // rows t0-5 .. t0+63, padded
    int b  = blockIdx.z;
    int o0 = blockIdx.y * 16;
    int t0 = blockIdx.x * 64;
    int tid = threadIdx.x;

    for (int idx = tid; idx < 16 * 384; idx += 128) {
        int oo = idx / 384, kk = idx % 384;
        int j = kk >> 6, i = kk & 63;
        Ws[oo][kk] = Wqk[(size_t)(o0 + oo) * 384 + i * QLc + j];
    }
    for (int idx = tid; idx < 69 * 64; idx += 128) {
        int rr = idx >> 6, i = idx & 63;
        int t = t0 - 5 + rr;
        Xs[rr][i] = (t >= 0) ? x[((size_t)b * Tc + t) * Ec + i] : 0.f;
    }
    __syncthreads();

    int ox = tid & 7;    // 8 groups, 2 channels each
    int tx = tid >> 3;   // 16 groups, 4 timesteps each
    float acc[2][4];
    #pragma unroll
    for (int a = 0; a < 2; a++)
        #pragma unroll
        for (int bb = 0; bb < 4; bb++) acc[a][bb] = 0.f;

    for (int kk = 0; kk < 384; kk++) {
        int j = kk >> 6, i = kk & 63;
        float w0 = Ws[ox * 2 + 0][kk];
        float w1 = Ws[ox * 2 + 1][kk];
        #pragma unroll
        for (int bb = 0; bb < 4; bb++) {
            float xv = Xs[tx * 4 + bb + j][i];
            acc[0][bb] += w0 * xv;
            acc[1][bb] += w1 * xv;
        }
    }
    #pragma unroll
    for (int a = 0; a < 2; a++) {
        int ch = o0 + ox * 2 + a;
        float bias = bqk[ch];
        int hh = (ch & 511) >> 6, e = ch & 63;
        float* dst = (ch < 512 ? g_Q : g_K) +
                     ((size_t)b * Hc + hh) * Tc * Ec + e;
        #pragma unroll
        for (int bb = 0; bb < 4; bb++) {
            int t = t0 + tx * 4 + bb;
            dst[(size_t)t * Ec] = acc[a][bb] + bias;
        }
    }
}

// ---------------------------------------------------------------------------
// Sparse masked attention: one warp per query row.
// QK dots use 8-lane-cooperative row loads (full-128B wavefronts).
// Each warp also ZEROES its own output weight row (replaces the memset pass).
// ---------------------------------------------------------------------------
__global__ void attn_kernel(float* __restrict__ wout_base) {
    __shared__ float sc[8][CAP];
    int w = threadIdx.x >> 5;
    int lane = threadIdx.x & 31;
    int sub = lane & 7;          // e-chunk owner (8 lanes per K row)
    int grp = lane >> 3;         // column group 0..3
    int r = blockIdx.x * 8 + w;
    int bh = blockIdx.y;

    // Q chunk in registers: e in [sub*8, sub*8+8)
    const float* Qrow = g_Q + ((size_t)bh * Tc + r) * Ec;
    float4 q0 = *(const float4*)(Qrow + sub * 8);
    float4 q1 = *(const float4*)(Qrow + sub * 8 + 4);

    // Zero this row of the weights output (coalesced, replaces memset)
    float* wout = wout_base + ((size_t)bh * Tc + r) * Tc;
    float4 z4 = make_float4(0.f, 0.f, 0.f, 0.f);
    #pragma unroll
    for (int s = 0; s < 16; s++)
        ((float4*)wout)[s * 32 + lane] = z4;

    int cnt = g_cnt[r];
    const unsigned short* cl = g_cols + r * CAP;
    const float* Kb = g_K + (size_t)bh * Tc * Ec;

    // Scores: warp handles 4 columns per step; 8 lanes per column row.
    float m = -1e30f;
    for (int j0 = 0; j0 < cnt; j0 += 4) {
        int jj = j0 + grp;
        int c = cl[jj < cnt ? jj : cnt - 1];
        const float4* kr = (const float4*)(Kb + (size_t)c * Ec + sub * 8);
        float4 k0 = kr[0], k1 = kr[1];
        float p = q0.x * k0.x + q0.y * k0.y + q0.z * k0.z + q0.w * k0.w
                + q1.x * k1.x + q1.y * k1.y + q1.z * k1.z + q1.w * k1.w;
        p += __shfl_down_sync(0xffffffffu, p, 4);
        p += __shfl_down_sync(0xffffffffu, p, 2);
        p += __shfl_down_sync(0xffffffffu, p, 1);
        float s = p * 0.125f;     // 1/sqrt(64)
        if (sub == 0 && jj < cnt) {
            sc[w][jj] = s;
            m = fmaxf(m, s);
        }
    }
    #pragma unroll
    for (int off = 16; off; off >>= 1)
        m = fmaxf(m, __shfl_xor_sync(0xffffffffu, m, off));
    __syncwarp();

    // exp + sum
    float sum = 0.f;
    for (int jj = lane; jj < cnt; jj += 32) {
        float e = __expf(sc[w][jj] - m);
        sc[w][jj] = e;
        sum += e;
    }
    #pragma unroll
    for (int off = 16; off; off >>= 1)
        sum += __shfl_xor_sync(0xffffffffu, sum, off);
    float inv = __fdividef(1.f, sum);
    __syncwarp();

    // scattered weight writes (row already zeroed by this warp; __syncwarp
    // above orders the zero-stores before these)
    for (int jj = lane; jj < cnt; jj += 32)
        wout[cl[jj]] = sc[w][jj] * inv;

    // PV accumulate: lanes own e-dims, coalesced V row reads
    const float* Vb = g_V + (size_t)bh * Tc * Ec;
    float o0 = 0.f, o1 = 0.f;
    int jj = 0;
    for (; jj + 4 <= cnt; jj += 4) {
        #pragma unroll
        for (int u = 0; u < 4; u++) {
            float wg = sc[w][jj + u];
            const float* vr = Vb + (size_t)cl[jj + u] * Ec;
            o0 += wg * vr[lane];
            o1 += wg * vr[lane + 32];
        }
    }
    for (; jj < cnt; jj++) {
        float wg = sc[w][jj];
        const float* vr = Vb + (size_t)cl[jj] * Ec;
        o0 += wg * vr[lane];
        o1 += wg * vr[lane + 32];
    }
    float* ar = g_ATT + ((size_t)bh * Tc + r) * Ec;
    ar[lane]      = o0 * inv;
    ar[lane + 32] = o1 * inv;
}

// ---------------------------------------------------------------------------
// Output projection: out[b,t,:] = attn_flat[b,t,:] @ Wp + bp
// ---------------------------------------------------------------------------
__global__ void proj_out(const float* __restrict__ Wp,
                         const float* __restrict__ bp,
                         float* __restrict__ out) {
    __shared__ float as[4][520];
    int base_bt = blockIdx.x * 4;
    int tid = threadIdx.x;   // 256
    for (int idx = tid; idx < 4 * 512; idx += 256) {
        int rr = idx >> 9, c = idx & 511;
        int bt = base_bt + rr;
        int b = bt / Tc, t = bt % Tc;
        int h = c >> 6, e = c & 63;
        as[rr][c] = g_ATT[(((size_t)b * Hc + h) * Tc + t) * Ec + e];
    }
    __syncthreads();
    int rr = tid >> 6, eo = tid & 63;
    float acc = bp[eo];
    for (int c = 0; c < 512; c++)
        acc += as[rr][c] * Wp[(size_t)c * Ec + eo];
    out[(size_t)(base_bt + rr) * Ec + eo] = acc;
}

// ---------------------------------------------------------------------------
extern "C" void kernel_launch(void* const* d_in, const int* in_sizes, int n_in,
                              void* d_out, int out_size) {
    const float* x    = (const float*)d_in[0];
    const float* Wqk  = (const float*)d_in[1];
    const float* bqk  = (const float*)d_in[2];
    const float* Wv   = (const float*)d_in[3];
    const float* bv   = (const float*)d_in[4];
    const float* Wp   = (const float*)d_in[5];
    const float* bp   = (const float*)d_in[6];
    // d_in[7] (mask) intentionally unused: regenerated on-device.

    float* out = (float*)d_out;
    float* weights = out + (size_t)Bc * Tc * Ec;  // attn_weights after out

    build_cols<<<(Tc + 127) / 128, 128>>>();
    proj_v<<<Bc * Tc, 128>>>(x, Wv, bv);
    dim3 gqk(Tc / 64, 1024 / 16, Bc);
    proj_qk<<<gqk, 128>>>(x, Wqk, bqk);
    dim3 ga(Tc / 8, BHc);
    attn_kernel<<<ga, 256>>>(weights);
    proj_out<<<Bc * Tc / 4, 256>>>(Wp, bp, out);
}